// round 1
// baseline (speedup 1.0000x reference)
#include <cuda_runtime.h>
#include <math.h>

#define BB 4
#define T 1024
#define C 1024
#define BT (BB*T)
#define NH 16
#define NKV 4
#define HD 64
#define FFNH 4096
#define CADIM 32
#define VECH 12

// ---------------- scratch (device globals; no runtime allocation) ----------------
__device__ float g_XN[BT*C];
__device__ float g_Q[BT*NH*HD];
__device__ float g_Kb[BT*NKV*HD];
__device__ float g_Vb[BT*NKV*HD];
__device__ float g_Y[BT*C];
__device__ float g_ATT[BT*C];
__device__ float g_X1[BT*C];
__device__ float g_XM[BT*C];
__device__ float g_H[BT*FFNH];
__device__ float g_H2[BT*FFNH];
__device__ float g_GATE[BT*C];
__device__ float g_MLP[BT*C];
__device__ float g_CR[BT*CADIM];
__device__ float g_CA1[BT*CADIM];
__device__ float g_CA2[BT*CADIM];
__device__ float g_VR[BT*CADIM];
__device__ float g_VIT[BT];
__device__ float g_VITF[BT];

// ---------------- rmsnorm over last dim C ----------------
__global__ void k_rmsnorm(const float* __restrict__ x, float* __restrict__ y) {
    int t = blockIdx.x;
    __shared__ float sx[C];
    __shared__ float red[8];
    const float* xr = x + (size_t)t * C;
    float ss = 0.f;
    for (int i = threadIdx.x; i < C; i += 256) { float v = xr[i]; sx[i] = v; ss += v * v; }
    #pragma unroll
    for (int o = 16; o; o >>= 1) ss += __shfl_xor_sync(0xffffffffu, ss, o);
    if ((threadIdx.x & 31) == 0) red[threadIdx.x >> 5] = ss;
    __syncthreads();
    if (threadIdx.x < 8) {
        float v = red[threadIdx.x];
        #pragma unroll
        for (int o = 4; o; o >>= 1) v += __shfl_xor_sync(0xffu, v, o);
        if (threadIdx.x == 0) red[0] = v;
    }
    __syncthreads();
    float sc = rsqrtf(red[0] / (float)C + 1e-6f);
    float* yr = y + (size_t)t * C;
    for (int i = threadIdx.x; i < C; i += 256) yr[i] = sx[i] * sc;
}

// ---------------- generic SGEMM: C[M,N] = A[M,K] @ W[N,K]^T ----------------
// 128x128x8 tiles, 256 threads, 8x8 microtile. EPI: 0=none 1=relu^2 2=sigmoid
template<int EPI>
__global__ void k_sgemm(const float* __restrict__ A, const float* __restrict__ W,
                        float* __restrict__ Cout, int M, int N, int K) {
    __shared__ float As[8][128];
    __shared__ float Bs[8][128];
    int tid = threadIdx.x;
    int bm = blockIdx.y * 128, bn = blockIdx.x * 128;
    int tx = tid & 15, ty = tid >> 4;
    int lr = tid >> 1;
    int lk = (tid & 1) * 4;
    const float* Ag = A + (size_t)(bm + lr) * K + lk;
    const float* Wg = W + (size_t)(bn + lr) * K + lk;
    float acc[8][8];
    #pragma unroll
    for (int i = 0; i < 8; i++)
        #pragma unroll
        for (int j = 0; j < 8; j++) acc[i][j] = 0.f;

    for (int k0 = 0; k0 < K; k0 += 8) {
        float4 av = *(const float4*)(Ag + k0);
        float4 wv = *(const float4*)(Wg + k0);
        As[lk + 0][lr] = av.x; As[lk + 1][lr] = av.y; As[lk + 2][lr] = av.z; As[lk + 3][lr] = av.w;
        Bs[lk + 0][lr] = wv.x; Bs[lk + 1][lr] = wv.y; Bs[lk + 2][lr] = wv.z; Bs[lk + 3][lr] = wv.w;
        __syncthreads();
        #pragma unroll
        for (int kk = 0; kk < 8; kk++) {
            float a[8], b[8];
            *(float4*)(a)     = *(const float4*)&As[kk][ty * 4];
            *(float4*)(a + 4) = *(const float4*)&As[kk][64 + ty * 4];
            *(float4*)(b)     = *(const float4*)&Bs[kk][tx * 4];
            *(float4*)(b + 4) = *(const float4*)&Bs[kk][64 + tx * 4];
            #pragma unroll
            for (int i = 0; i < 8; i++)
                #pragma unroll
                for (int j = 0; j < 8; j++) acc[i][j] = fmaf(a[i], b[j], acc[i][j]);
        }
        __syncthreads();
    }
    #pragma unroll
    for (int i = 0; i < 8; i++) {
        int r = (i < 4) ? (ty * 4 + i) : (64 + ty * 4 + i - 4);
        #pragma unroll
        for (int j = 0; j < 8; j++) {
            int c = (j < 4) ? (tx * 4 + j) : (64 + tx * 4 + j - 4);
            float v = acc[i][j];
            if (EPI == 1) { float rr = fmaxf(v, 0.f); v = rr * rr; }
            if (EPI == 2) { v = 1.f / (1.f + expf(-v)); }
            Cout[(size_t)(bm + r) * N + bn + c] = v;
        }
    }
}

// ---------------- gate + rope + per-head rmsnorm ----------------
__global__ void k_ropegate(float* __restrict__ Qb, float* __restrict__ Kb, float* __restrict__ Vb,
                           const float* __restrict__ XN, const float* __restrict__ ve,
                           const float* __restrict__ cosb, const float* __restrict__ sinb,
                           const float* __restrict__ wveg) {
    int t = blockIdx.x;
    int tt = t & (T - 1);
    __shared__ float sq[NH * HD];
    __shared__ float sr[NH * HD];
    __shared__ float gsm[NKV];
    int tid = threadIdx.x;
    if (tid < NKV) {
        float s = 0.f;
        #pragma unroll
        for (int j = 0; j < VECH; j++) s += XN[(size_t)t * C + j] * wveg[tid * VECH + j];
        gsm[tid] = 3.f / (1.f + expf(-s));
    }
    for (int i = tid; i < NH * HD; i += 256) sq[i] = Qb[(size_t)t * NH * HD + i];
    __syncthreads();
    for (int i = tid; i < NH * HD; i += 256) {
        int hh = i >> 6, d = i & 63;
        float val;
        if (d < 32) {
            float cv = cosb[tt * 32 + d], sv = sinb[tt * 32 + d];
            val = sq[hh * 64 + d] * cv + sq[hh * 64 + d + 32] * sv;
        } else {
            int d2 = d - 32;
            float cv = cosb[tt * 32 + d2], sv = sinb[tt * 32 + d2];
            val = -sq[hh * 64 + d2] * sv + sq[hh * 64 + d] * cv;
        }
        sr[i] = val;
    }
    __syncthreads();
    int w = tid >> 5, lane = tid & 31;
    for (int hh = w; hh < NH; hh += 8) {
        float v0 = sr[hh * 64 + lane], v1 = sr[hh * 64 + 32 + lane];
        float ss = v0 * v0 + v1 * v1;
        #pragma unroll
        for (int o = 16; o; o >>= 1) ss += __shfl_xor_sync(0xffffffffu, ss, o);
        float sc = rsqrtf(ss / 64.f + 1e-6f) * 1.2f;
        Qb[(size_t)t * NH * HD + hh * 64 + lane] = v0 * sc;
        Qb[(size_t)t * NH * HD + hh * 64 + 32 + lane] = v1 * sc;
    }
    __syncthreads();
    // K heads
    for (int i = tid; i < NKV * HD; i += 256) sq[i] = Kb[(size_t)t * NKV * HD + i];
    __syncthreads();
    for (int i = tid; i < NKV * HD; i += 256) {
        int hh = i >> 6, d = i & 63;
        float val;
        if (d < 32) {
            float cv = cosb[tt * 32 + d], sv = sinb[tt * 32 + d];
            val = sq[hh * 64 + d] * cv + sq[hh * 64 + d + 32] * sv;
        } else {
            int d2 = d - 32;
            float cv = cosb[tt * 32 + d2], sv = sinb[tt * 32 + d2];
            val = -sq[hh * 64 + d2] * sv + sq[hh * 64 + d] * cv;
        }
        sr[i] = val;
    }
    __syncthreads();
    if (w < NKV) {
        int hh = w;
        float v0 = sr[hh * 64 + lane], v1 = sr[hh * 64 + 32 + lane];
        float ss = v0 * v0 + v1 * v1;
        #pragma unroll
        for (int o = 16; o; o >>= 1) ss += __shfl_xor_sync(0xffffffffu, ss, o);
        float sc = rsqrtf(ss / 64.f + 1e-6f) * 1.2f;
        Kb[(size_t)t * NKV * HD + hh * 64 + lane] = v0 * sc;
        Kb[(size_t)t * NKV * HD + hh * 64 + 32 + lane] = v1 * sc;
    }
    // V gating (all 256 threads, one element each)
    {
        int hh = tid >> 6;
        size_t idx = (size_t)t * NKV * HD + tid;
        Vb[idx] = Vb[idx] + gsm[hh] * ve[idx];
    }
}

// ---------------- flash attention with refine conv ----------------
// grid: (T/64, NH, B), 256 threads, dynamic smem
__global__ void k_flash(const float* __restrict__ Qb, const float* __restrict__ Kb,
                        const float* __restrict__ Vb, const float* __restrict__ prev,
                        const float* __restrict__ rw, const float* __restrict__ alphap,
                        float* __restrict__ Y) {
    extern __shared__ float sm[];
    float* Qs = sm;               // 64*65
    float* Ks = Qs + 64 * 65;     // 64*65
    float* Vs = Ks + 64 * 65;     // 64*65
    float* Ss = Vs + 64 * 65;     // 64*65
    float* Ps = Ss + 64 * 65;     // 66*66
    float* mrow = Ps + 66 * 66;   // 64
    float* lrow = mrow + 64;      // 64
    float* crow = lrow + 64;      // 64
    int tid = threadIdx.x;
    int qt = blockIdx.x, h = blockIdx.y, b = blockIdx.z;
    int q0 = qt * 64;
    int hk = h >> 2;
    float alpha = alphap[0];
    float w9[9];
    #pragma unroll
    for (int i = 0; i < 9; i++) w9[i] = rw[h * 9 + i];

    for (int idx = tid; idx < 64 * 64; idx += 256) {
        int r = idx >> 6, d = idx & 63;
        Qs[r * 65 + d] = Qb[(((size_t)(b * T) + q0 + r) * NH + h) * HD + d];
    }
    if (tid < 64) { mrow[tid] = -INFINITY; lrow[tid] = 0.f; }
    int ty = tid >> 4, tx = tid & 15;
    float o[4][4];
    #pragma unroll
    for (int i = 0; i < 4; i++)
        #pragma unroll
        for (int j = 0; j < 4; j++) o[i][j] = 0.f;

    int nkt = qt + 1;
    for (int kt = 0; kt < nkt; kt++) {
        int k0 = kt * 64;
        __syncthreads();
        for (int idx = tid; idx < 64 * 64; idx += 256) {
            int r = idx >> 6, d = idx & 63;
            size_t base = ((size_t)(b * T) + k0 + r) * NKV + hk;
            Ks[r * 65 + d] = Kb[base * HD + d];
            Vs[r * 65 + d] = Vb[base * HD + d];
        }
        for (int idx = tid; idx < 66 * 66; idx += 256) {
            int li = idx / 66, lj = idx % 66;
            int gi = q0 - 1 + li, gj = k0 - 1 + lj;
            float v = 0.f;
            if (gi >= 0 && gi < T && gj >= 0 && gj < T)
                v = prev[(((size_t)(b * NH) + h) * T + gi) * T + gj];
            Ps[li * 66 + lj] = v;
        }
        __syncthreads();
        float s[4][4];
        #pragma unroll
        for (int i = 0; i < 4; i++)
            #pragma unroll
            for (int j = 0; j < 4; j++) s[i][j] = 0.f;
        #pragma unroll 4
        for (int d = 0; d < HD; d++) {
            float a[4], bv[4];
            #pragma unroll
            for (int i = 0; i < 4; i++) a[i] = Qs[(ty * 4 + i) * 65 + d];
            #pragma unroll
            for (int j = 0; j < 4; j++) bv[j] = Ks[(tx * 4 + j) * 65 + d];
            #pragma unroll
            for (int i = 0; i < 4; i++)
                #pragma unroll
                for (int j = 0; j < 4; j++) s[i][j] = fmaf(a[i], bv[j], s[i][j]);
        }
        #pragma unroll
        for (int i = 0; i < 4; i++) {
            int ri = ty * 4 + i;
            #pragma unroll
            for (int j = 0; j < 4; j++) {
                int cj = tx * 4 + j;
                float v = s[i][j] * 0.125f;
                float cv = 0.f;
                #pragma unroll
                for (int a = 0; a < 3; a++)
                    #pragma unroll
                    for (int bb = 0; bb < 3; bb++)
                        cv = fmaf(w9[a * 3 + bb], Ps[(ri + a) * 66 + cj + bb], cv);
                v += alpha * cv;
                if (k0 + cj > q0 + ri) v = -INFINITY;
                Ss[ri * 65 + cj] = v;
            }
        }
        __syncthreads();
        if (tid < 64) {
            int r = tid;
            float mo = mrow[r];
            float rm = -INFINITY;
            for (int j = 0; j < 64; j++) rm = fmaxf(rm, Ss[r * 65 + j]);
            float nm = fmaxf(mo, rm);
            float corr = expf(mo - nm);
            float sum = 0.f;
            for (int j = 0; j < 64; j++) {
                float p = expf(Ss[r * 65 + j] - nm);
                Ss[r * 65 + j] = p;
                sum += p;
            }
            mrow[r] = nm;
            lrow[r] = lrow[r] * corr + sum;
            crow[r] = corr;
        }
        __syncthreads();
        #pragma unroll
        for (int i = 0; i < 4; i++) {
            float cc = crow[ty * 4 + i];
            #pragma unroll
            for (int j = 0; j < 4; j++) o[i][j] *= cc;
        }
        #pragma unroll 4
        for (int j = 0; j < 64; j++) {
            float a[4], bv[4];
            #pragma unroll
            for (int i = 0; i < 4; i++) a[i] = Ss[(ty * 4 + i) * 65 + j];
            #pragma unroll
            for (int jj = 0; jj < 4; jj++) bv[jj] = Vs[j * 65 + tx * 4 + jj];
            #pragma unroll
            for (int i = 0; i < 4; i++)
                #pragma unroll
                for (int jj = 0; jj < 4; jj++) o[i][jj] = fmaf(a[i], bv[jj], o[i][jj]);
        }
    }
    #pragma unroll
    for (int i = 0; i < 4; i++) {
        int ri = ty * 4 + i;
        float inv = 1.f / lrow[ri];
        #pragma unroll
        for (int j = 0; j < 4; j++) {
            int cj = tx * 4 + j;
            Y[(((size_t)(b * T) + q0 + ri) * NH + h) * HD + cj] = o[i][j] * inv;
        }
    }
}

// ---------------- 32-dim projection: OUT[t][o] = X[t] . W[o] ----------------
__global__ void k_dot32(const float* __restrict__ X, const float* __restrict__ W,
                        float* __restrict__ OUT) {
    __shared__ float sx[8 * C];
    int t0 = blockIdx.x * 8;
    for (int i = threadIdx.x; i < 8 * C; i += 256) sx[i] = X[(size_t)t0 * C + i];
    __syncthreads();
    int tok = threadIdx.x >> 5, o = threadIdx.x & 31;
    const float4* wr = (const float4*)(W + (size_t)o * C);
    const float4* xr = (const float4*)(sx + tok * C);
    float s = 0.f;
    #pragma unroll 4
    for (int k = 0; k < C / 4; k++) {
        float4 a = xr[k], b = wr[k];
        s += a.x * b.x + a.y * b.y + a.z * b.z + a.w * b.w;
    }
    OUT[(size_t)(t0 + tok) * CADIM + o] = s;
}

// ---------------- ca channel: h + 0.1*dwconvT(h), then exact gelu ----------------
__global__ void k_caconv(const float* __restrict__ R, const float* __restrict__ cw,
                         float* __restrict__ OUT) {
    int b = blockIdx.y, t0 = blockIdx.x * 128;
    __shared__ float s[130 * 32];
    __shared__ float w[32 * 3];
    for (int i = threadIdx.x; i < 96; i += 256) w[i] = cw[i];
    for (int i = threadIdx.x; i < 130 * 32; i += 256) {
        int r = i >> 5, c = i & 31;
        int t = t0 - 1 + r;
        s[i] = (t >= 0 && t < T) ? R[((size_t)(b * T) + t) * CADIM + c] : 0.f;
    }
    __syncthreads();
    for (int i = threadIdx.x; i < 128 * 32; i += 256) {
        int r = i >> 5, c = i & 31;
        float h0 = s[(r + 1) * 32 + c];
        float cv = w[c * 3 + 0] * s[r * 32 + c] + w[c * 3 + 1] * h0 + w[c * 3 + 2] * s[(r + 2) * 32 + c];
        float v = h0 + 0.1f * cv;
        v = 0.5f * v * (1.f + erff(v * 0.70710678118f));
        OUT[((size_t)(b * T) + t0 + r) * CADIM + c] = v;
    }
}

// ---------------- x1 = x + attn*(1 + 0.1*tanh(cah @ ca_po^T)) ----------------
__global__ void k_x1(const float* __restrict__ x, const float* __restrict__ attn,
                     const float* __restrict__ cah, const float* __restrict__ capo,
                     float* __restrict__ X1) {
    int tg = blockIdx.x;  // 16 tokens each
    __shared__ float h[16 * 32];
    __shared__ float po[256 * 33];
    int tid = threadIdx.x;
    for (int i = tid; i < 16 * 32; i += 256) h[i] = cah[(size_t)tg * 16 * 32 + i];
    for (int cc = 0; cc < 4; cc++) {
        int c0 = cc * 256;
        __syncthreads();
        for (int i = tid; i < 256 * 32; i += 256) po[(i >> 5) * 33 + (i & 31)] = capo[(size_t)c0 * 32 + i];
        __syncthreads();
        float wv[32];
        #pragma unroll
        for (int j = 0; j < 32; j++) wv[j] = po[tid * 33 + j];
        int c = c0 + tid;
        for (int tok = 0; tok < 16; tok++) {
            float ca = 0.f;
            #pragma unroll
            for (int j = 0; j < 32; j++) ca = fmaf(wv[j], h[tok * 32 + j], ca);
            size_t idx = ((size_t)tg * 16 + tok) * C + c;
            X1[idx] = x[idx] + attn[idx] * (1.f + 0.1f * tanhf(ca));
        }
    }
}

// ---------------- FFN depthwise conv along T, 4 fused iterations ----------------
__global__ void k_ffnconv(const float* __restrict__ Hin, const float* __restrict__ cw,
                          float* __restrict__ Hout) {
    int c0 = blockIdx.x * 32, t0 = blockIdx.y * 64, b = blockIdx.z;
    __shared__ float bufA[72 * 32];
    __shared__ float bufB[72 * 32];
    __shared__ float w[32 * 3];
    int tid = threadIdx.x;
    for (int i = tid; i < 96; i += 256) w[i] = cw[(size_t)c0 * 3 + i];
    for (int i = tid; i < 72 * 32; i += 256) {
        int r = i >> 5, c = i & 31;
        int t = t0 - 4 + r;
        bufA[i] = (t >= 0 && t < T) ? Hin[((size_t)(b * T) + t) * FFNH + c0 + c] : 0.f;
    }
    float* A = bufA;
    float* Bf = bufB;
    for (int it = 0; it < 4; it++) {
        __syncthreads();
        for (int i = tid; i < 72 * 32; i += 256) {
            int r = i >> 5, c = i & 31;
            int t = t0 - 4 + r;
            float v = 0.f;
            if (t >= 0 && t < T) {
                float am = (r > 0) ? A[(r - 1) * 32 + c] : 0.f;
                float a0 = A[i];
                float ap = (r < 71) ? A[(r + 1) * 32 + c] : 0.f;
                v = a0 + 0.1f * (w[c * 3] * am + w[c * 3 + 1] * a0 + w[c * 3 + 2] * ap);
            }
            Bf[i] = v;
        }
        float* tmp = A; A = Bf; Bf = tmp;
    }
    __syncthreads();
    for (int i = tid; i < 64 * 32; i += 256) {
        int r = i >> 5, c = i & 31;
        Hout[((size_t)(b * T) + t0 + r) * FFNH + c0 + c] = A[(r + 4) * 32 + c];
    }
}

// ---------------- vit head ----------------
__global__ void k_vitpost(const float* __restrict__ VR, const float* __restrict__ w2,
                          float* __restrict__ VIT) {
    int t = blockIdx.x * 256 + threadIdx.x;
    float s = 0.f;
    #pragma unroll
    for (int j = 0; j < 32; j++) {
        float v = VR[(size_t)t * 32 + j];
        v = 0.5f * v * (1.f + erff(v * 0.70710678118f));
        s += v * w2[j];
    }
    VIT[t] = 1.f / (1.f + expf(-s));
}

__global__ void k_vsmooth(const float* __restrict__ VIT, float* __restrict__ VITF) {
    int b = blockIdx.x;
    for (int t = threadIdx.x; t < T; t += 256) {
        float v = VIT[b * T + t];
        float s = 0.f;
        #pragma unroll
        for (int d = -2; d <= 2; d++) {
            int tt = t + d;
            if (tt >= 0 && tt < T) s += VIT[b * T + tt];
        }
        s *= 0.2f;
        float f = 0.7f * v + 0.3f * s;
        VITF[b * T + t] = (f > 0.3f) ? f : 0.1f * f;
    }
}

// ---------------- out = x1 + mlp*gate*(1+0.1*tanh(ca2))*vit ----------------
__global__ void k_final(const float* __restrict__ x1, const float* __restrict__ mlp,
                        const float* __restrict__ gate, const float* __restrict__ cah,
                        const float* __restrict__ capo, const float* __restrict__ vitf,
                        float* __restrict__ out) {
    int tg = blockIdx.x;
    __shared__ float h[16 * 32];
    __shared__ float po[256 * 33];
    __shared__ float sv[16];
    int tid = threadIdx.x;
    for (int i = tid; i < 16 * 32; i += 256) h[i] = cah[(size_t)tg * 16 * 32 + i];
    if (tid < 16) sv[tid] = vitf[tg * 16 + tid];
    for (int cc = 0; cc < 4; cc++) {
        int c0 = cc * 256;
        __syncthreads();
        for (int i = tid; i < 256 * 32; i += 256) po[(i >> 5) * 33 + (i & 31)] = capo[(size_t)c0 * 32 + i];
        __syncthreads();
        float wv[32];
        #pragma unroll
        for (int j = 0; j < 32; j++) wv[j] = po[tid * 33 + j];
        int c = c0 + tid;
        for (int tok = 0; tok < 16; tok++) {
            float ca = 0.f;
            #pragma unroll
            for (int j = 0; j < 32; j++) ca = fmaf(wv[j], h[tok * 32 + j], ca);
            size_t idx = ((size_t)tg * 16 + tok) * C + c;
            float m = mlp[idx] * gate[idx] * (1.f + 0.1f * tanhf(ca)) * sv[tok];
            out[idx] = x1[idx] + m;
        }
    }
}

// ---------------- host ----------------
extern "C" void kernel_launch(void* const* d_in, const int* in_sizes, int n_in,
                              void* d_out, int out_size) {
    const float* x        = (const float*)d_in[0];
    const float* ve       = (const float*)d_in[1];
    const float* cosb     = (const float*)d_in[2];
    const float* sinb     = (const float*)d_in[3];
    const float* prev     = (const float*)d_in[4];
    const float* w_q      = (const float*)d_in[5];
    const float* w_k      = (const float*)d_in[6];
    const float* w_v      = (const float*)d_in[7];
    const float* w_o      = (const float*)d_in[8];
    const float* w_veg    = (const float*)d_in[9];
    const float* refine_w = (const float*)d_in[10];
    const float* alpha    = (const float*)d_in[11];
    const float* ca_pi    = (const float*)d_in[12];
    const float* ca_cw    = (const float*)d_in[13];
    const float* ca_po    = (const float*)d_in[14];
    const float* ffn_in   = (const float*)d_in[15];
    const float* ffn_cw   = (const float*)d_in[16];
    const float* ffn_out  = (const float*)d_in[17];
    const float* ffn_gate = (const float*)d_in[18];
    const float* vit_w1   = (const float*)d_in[19];
    const float* vit_w2   = (const float*)d_in[20];
    float* out = (float*)d_out;

    float *XN, *Qp, *Kp, *Vp, *Yp, *ATT, *X1, *XM, *Hp, *H2, *GATE, *MLP, *CR, *CA1, *CA2, *VR, *VIT, *VITF;
    cudaGetSymbolAddress((void**)&XN, g_XN);
    cudaGetSymbolAddress((void**)&Qp, g_Q);
    cudaGetSymbolAddress((void**)&Kp, g_Kb);
    cudaGetSymbolAddress((void**)&Vp, g_Vb);
    cudaGetSymbolAddress((void**)&Yp, g_Y);
    cudaGetSymbolAddress((void**)&ATT, g_ATT);
    cudaGetSymbolAddress((void**)&X1, g_X1);
    cudaGetSymbolAddress((void**)&XM, g_XM);
    cudaGetSymbolAddress((void**)&Hp, g_H);
    cudaGetSymbolAddress((void**)&H2, g_H2);
    cudaGetSymbolAddress((void**)&GATE, g_GATE);
    cudaGetSymbolAddress((void**)&MLP, g_MLP);
    cudaGetSymbolAddress((void**)&CR, g_CR);
    cudaGetSymbolAddress((void**)&CA1, g_CA1);
    cudaGetSymbolAddress((void**)&CA2, g_CA2);
    cudaGetSymbolAddress((void**)&VR, g_VR);
    cudaGetSymbolAddress((void**)&VIT, g_VIT);
    cudaGetSymbolAddress((void**)&VITF, g_VITF);

    // 1. xn = rmsnorm(x)
    k_rmsnorm<<<BT, 256>>>(x, XN);

    // 2. projections
    dim3 g1(C / 128, BT / 128);
    dim3 g2((NKV * HD) / 128, BT / 128);
    k_sgemm<0><<<g1, 256>>>(XN, w_q, Qp, BT, C, C);
    k_sgemm<0><<<g2, 256>>>(XN, w_k, Kp, BT, NKV * HD, C);
    k_sgemm<0><<<g2, 256>>>(XN, w_v, Vp, BT, NKV * HD, C);

    // 3. gate + rope + head rmsnorm
    k_ropegate<<<BT, 256>>>(Qp, Kp, Vp, XN, ve, cosb, sinb, w_veg);

    // 4. flash attention with refine conv
    int smemf = (4 * 64 * 65 + 66 * 66 + 3 * 64) * (int)sizeof(float);
    cudaFuncSetAttribute(k_flash, cudaFuncAttributeMaxDynamicSharedMemorySize, smemf);
    dim3 gf(T / 64, NH, BB);
    k_flash<<<gf, 256, smemf>>>(Qp, Kp, Vp, prev, refine_w, alpha, Yp);

    // 5. output projection
    k_sgemm<0><<<g1, 256>>>(Yp, w_o, ATT, BT, C, C);

    // 6. ca1 + x1
    k_dot32<<<BT / 8, 256>>>(x, ca_pi, CR);
    dim3 gc(T / 128, BB);
    k_caconv<<<gc, 256>>>(CR, ca_cw, CA1);
    k_x1<<<BT / 16, 256>>>(x, ATT, CA1, ca_po, X1);

    // 7. FFN
    k_rmsnorm<<<BT, 256>>>(X1, XM);
    dim3 g3(FFNH / 128, BT / 128);
    k_sgemm<1><<<g3, 256>>>(XM, ffn_in, Hp, BT, FFNH, C);
    dim3 g4(FFNH / 32, T / 64, BB);
    k_ffnconv<<<g4, 256>>>(Hp, ffn_cw, H2);
    k_sgemm<2><<<g1, 256>>>(XM, ffn_gate, GATE, BT, C, C);
    k_sgemm<0><<<g1, 256>>>(H2, ffn_out, MLP, BT, C, FFNH);

    // 8. ca2, vit
    k_dot32<<<BT / 8, 256>>>(X1, ca_pi, CR);
    k_caconv<<<gc, 256>>>(CR, ca_cw, CA2);
    k_dot32<<<BT / 8, 256>>>(X1, vit_w1, VR);
    k_vitpost<<<BT / 256, 256>>>(VR, vit_w2, VIT);
    k_vsmooth<<<BB, 256>>>(VIT, VITF);

    // 9. final combine
    k_final<<<BT / 16, 256>>>(X1, MLP, GATE, CA2, ca_po, VITF, out);
}

// round 2
// speedup vs baseline: 1.9350x; 1.9350x over previous
#include <cuda_runtime.h>
#include <math.h>

#define BB 4
#define T 1024
#define C 1024
#define BT (BB*T)
#define NH 16
#define NKV 4
#define HD 64
#define FFNH 4096
#define CADIM 32
#define VECH 12
#define QKVW 1536
#define FW 5120

// ---------------- scratch ----------------
__device__ float g_XN[BT*C];
__device__ float g_QKV[BT*QKVW];
__device__ float g_WQKV[QKVW*C];
__device__ float g_Y[BT*C];
__device__ float g_ATT[BT*C];
__device__ float g_X1[BT*C];
__device__ float g_XM[BT*C];
__device__ float g_WF[FW*C];
__device__ float g_HG[(size_t)BT*FW];
__device__ float g_H2[(size_t)BT*FFNH];
__device__ float g_MLP[BT*C];
__device__ float g_CR[BT*CADIM];
__device__ float g_CA1[BT*CADIM];
__device__ float g_CA2[BT*CADIM];
__device__ float g_VR[BT*CADIM];
__device__ float g_VIT[BT];
__device__ float g_VITF[BT];

// ---------------- tf32 helpers ----------------
__device__ __forceinline__ unsigned f2tf(float x) {
    unsigned u; asm("cvt.rna.tf32.f32 %0, %1;" : "=r"(u) : "f"(x)); return u;
}
__device__ __forceinline__ void mma8(float* c, unsigned a0, unsigned a1, unsigned a2, unsigned a3,
                                     unsigned b0, unsigned b1) {
    asm("mma.sync.aligned.m16n8k8.row.col.f32.tf32.tf32.f32 "
        "{%0,%1,%2,%3},{%4,%5,%6,%7},{%8,%9},{%0,%1,%2,%3};"
        : "+f"(c[0]), "+f"(c[1]), "+f"(c[2]), "+f"(c[3])
        : "r"(a0), "r"(a1), "r"(a2), "r"(a3), "r"(b0), "r"(b1));
}

// ---------------- rmsnorm ----------------
__global__ void k_rmsnorm(const float* __restrict__ x, float* __restrict__ y) {
    int t = blockIdx.x;
    __shared__ float sx[C];
    __shared__ float red[8];
    const float* xr = x + (size_t)t * C;
    float ss = 0.f;
    for (int i = threadIdx.x; i < C; i += 256) { float v = xr[i]; sx[i] = v; ss += v * v; }
    #pragma unroll
    for (int o = 16; o; o >>= 1) ss += __shfl_xor_sync(0xffffffffu, ss, o);
    if ((threadIdx.x & 31) == 0) red[threadIdx.x >> 5] = ss;
    __syncthreads();
    if (threadIdx.x < 8) {
        float v = red[threadIdx.x];
        #pragma unroll
        for (int o = 4; o; o >>= 1) v += __shfl_xor_sync(0xffu, v, o);
        if (threadIdx.x == 0) red[0] = v;
    }
    __syncthreads();
    float sc = rsqrtf(red[0] / (float)C + 1e-6f);
    float* yr = y + (size_t)t * C;
    for (int i = threadIdx.x; i < C; i += 256) yr[i] = sx[i] * sc;
}

// ---------------- tf32 MMA GEMM: C[M,N] = A[M,K] @ W[N,K]^T ----------------
// 128x128 tile, BK=16, double-buffered. EPI: 0 none, 3 = (col<4096 relu^2 else sigmoid)
template<int EPI>
__global__ void __launch_bounds__(256) k_mgemm(const float* __restrict__ A, const float* __restrict__ W,
                                               float* __restrict__ Cout, int M, int N, int K) {
    __shared__ unsigned As[2][128][20];
    __shared__ unsigned Bs[2][128][20];
    const int tid = threadIdx.x, lane = tid & 31, w = tid >> 5;
    const int g = lane >> 2, t4 = lane & 3;
    const int wm = w >> 1, wn = w & 1;
    const int bm = blockIdx.y * 128, bn = blockIdx.x * 128;
    const int lr = tid >> 2, lc = (tid & 3) * 4;
    float acc[2][8][4];
    #pragma unroll
    for (int i = 0; i < 2; i++)
        #pragma unroll
        for (int j = 0; j < 8; j++)
            #pragma unroll
            for (int p = 0; p < 4; p++) acc[i][j][p] = 0.f;

    const float* Ap = A + (size_t)bm * K;
    const float* Wp = W + (size_t)bn * K;

    float4 ra0 = *(const float4*)&Ap[(size_t)lr * K + lc];
    float4 ra1 = *(const float4*)&Ap[(size_t)(lr + 64) * K + lc];
    float4 rb0 = *(const float4*)&Wp[(size_t)lr * K + lc];
    float4 rb1 = *(const float4*)&Wp[(size_t)(lr + 64) * K + lc];
    {
        uint4 u;
        u.x = f2tf(ra0.x); u.y = f2tf(ra0.y); u.z = f2tf(ra0.z); u.w = f2tf(ra0.w);
        *(uint4*)&As[0][lr][lc] = u;
        u.x = f2tf(ra1.x); u.y = f2tf(ra1.y); u.z = f2tf(ra1.z); u.w = f2tf(ra1.w);
        *(uint4*)&As[0][lr + 64][lc] = u;
        u.x = f2tf(rb0.x); u.y = f2tf(rb0.y); u.z = f2tf(rb0.z); u.w = f2tf(rb0.w);
        *(uint4*)&Bs[0][lr][lc] = u;
        u.x = f2tf(rb1.x); u.y = f2tf(rb1.y); u.z = f2tf(rb1.z); u.w = f2tf(rb1.w);
        *(uint4*)&Bs[0][lr + 64][lc] = u;
    }
    __syncthreads();

    const int nit = K / 16;
    for (int it = 0; it < nit; it++) {
        int buf = it & 1;
        if (it + 1 < nit) {
            int kn = (it + 1) * 16;
            ra0 = *(const float4*)&Ap[(size_t)lr * K + kn + lc];
            ra1 = *(const float4*)&Ap[(size_t)(lr + 64) * K + kn + lc];
            rb0 = *(const float4*)&Wp[(size_t)lr * K + kn + lc];
            rb1 = *(const float4*)&Wp[(size_t)(lr + 64) * K + kn + lc];
        }
        #pragma unroll
        for (int kk = 0; kk < 2; kk++) {
            unsigned a[2][4];
            #pragma unroll
            for (int mt = 0; mt < 2; mt++) {
                int r0 = wm * 32 + mt * 16;
                a[mt][0] = As[buf][r0 + g][kk * 8 + t4];
                a[mt][1] = As[buf][r0 + 8 + g][kk * 8 + t4];
                a[mt][2] = As[buf][r0 + g][kk * 8 + 4 + t4];
                a[mt][3] = As[buf][r0 + 8 + g][kk * 8 + 4 + t4];
            }
            #pragma unroll
            for (int nt = 0; nt < 8; nt++) {
                int c0 = wn * 64 + nt * 8;
                unsigned b0 = Bs[buf][c0 + g][kk * 8 + t4];
                unsigned b1 = Bs[buf][c0 + g][kk * 8 + 4 + t4];
                mma8(acc[0][nt], a[0][0], a[0][1], a[0][2], a[0][3], b0, b1);
                mma8(acc[1][nt], a[1][0], a[1][1], a[1][2], a[1][3], b0, b1);
            }
        }
        if (it + 1 < nit) {
            int nb = buf ^ 1;
            uint4 u;
            u.x = f2tf(ra0.x); u.y = f2tf(ra0.y); u.z = f2tf(ra0.z); u.w = f2tf(ra0.w);
            *(uint4*)&As[nb][lr][lc] = u;
            u.x = f2tf(ra1.x); u.y = f2tf(ra1.y); u.z = f2tf(ra1.z); u.w = f2tf(ra1.w);
            *(uint4*)&As[nb][lr + 64][lc] = u;
            u.x = f2tf(rb0.x); u.y = f2tf(rb0.y); u.z = f2tf(rb0.z); u.w = f2tf(rb0.w);
            *(uint4*)&Bs[nb][lr][lc] = u;
            u.x = f2tf(rb1.x); u.y = f2tf(rb1.y); u.z = f2tf(rb1.z); u.w = f2tf(rb1.w);
            *(uint4*)&Bs[nb][lr + 64][lc] = u;
        }
        __syncthreads();
    }

    #pragma unroll
    for (int mt = 0; mt < 2; mt++) {
        #pragma unroll
        for (int nt = 0; nt < 8; nt++) {
            int row = bm + wm * 32 + mt * 16 + g;
            int col = bn + wn * 64 + nt * 8 + 2 * t4;
            float v[4];
            #pragma unroll
            for (int p = 0; p < 4; p++) {
                float x = acc[mt][nt][p];
                if (EPI == 3) {
                    if (col < 4096) { float r = fmaxf(x, 0.f); x = r * r; }
                    else x = 1.f / (1.f + __expf(-x));
                }
                v[p] = x;
            }
            *(float2*)&Cout[(size_t)row * N + col] = make_float2(v[0], v[1]);
            *(float2*)&Cout[(size_t)(row + 8) * N + col] = make_float2(v[2], v[3]);
        }
    }
}

// ---------------- gate + rope + per-head rmsnorm (fused QKV layout) ----------------
__global__ void k_ropegate(float* __restrict__ QKV, const float* __restrict__ XN,
                           const float* __restrict__ ve, const float* __restrict__ cosb,
                           const float* __restrict__ sinb, const float* __restrict__ wveg) {
    int t = blockIdx.x;
    int tt = t & (T - 1);
    __shared__ float sq[NH * HD];
    __shared__ float sr[NH * HD];
    __shared__ float gsm[NKV];
    int tid = threadIdx.x;
    float* Qb = QKV + (size_t)t * QKVW;
    float* Kb = Qb + 1024;
    float* Vb = Qb + 1280;
    if (tid < NKV) {
        float s = 0.f;
        #pragma unroll
        for (int j = 0; j < VECH; j++) s += XN[(size_t)t * C + j] * wveg[tid * VECH + j];
        gsm[tid] = 3.f / (1.f + __expf(-s));
    }
    for (int i = tid; i < NH * HD; i += 256) sq[i] = Qb[i];
    __syncthreads();
    for (int i = tid; i < NH * HD; i += 256) {
        int hh = i >> 6, d = i & 63;
        float val;
        if (d < 32) {
            float cv = cosb[tt * 32 + d], sv = sinb[tt * 32 + d];
            val = sq[hh * 64 + d] * cv + sq[hh * 64 + d + 32] * sv;
        } else {
            int d2 = d - 32;
            float cv = cosb[tt * 32 + d2], sv = sinb[tt * 32 + d2];
            val = -sq[hh * 64 + d2] * sv + sq[hh * 64 + d] * cv;
        }
        sr[i] = val;
    }
    __syncthreads();
    int w = tid >> 5, lane = tid & 31;
    for (int hh = w; hh < NH; hh += 8) {
        float v0 = sr[hh * 64 + lane], v1 = sr[hh * 64 + 32 + lane];
        float ss = v0 * v0 + v1 * v1;
        #pragma unroll
        for (int o = 16; o; o >>= 1) ss += __shfl_xor_sync(0xffffffffu, ss, o);
        float sc = rsqrtf(ss / 64.f + 1e-6f) * 1.2f;
        Qb[hh * 64 + lane] = v0 * sc;
        Qb[hh * 64 + 32 + lane] = v1 * sc;
    }
    __syncthreads();
    for (int i = tid; i < NKV * HD; i += 256) sq[i] = Kb[i];
    __syncthreads();
    for (int i = tid; i < NKV * HD; i += 256) {
        int hh = i >> 6, d = i & 63;
        float val;
        if (d < 32) {
            float cv = cosb[tt * 32 + d], sv = sinb[tt * 32 + d];
            val = sq[hh * 64 + d] * cv + sq[hh * 64 + d + 32] * sv;
        } else {
            int d2 = d - 32;
            float cv = cosb[tt * 32 + d2], sv = sinb[tt * 32 + d2];
            val = -sq[hh * 64 + d2] * sv + sq[hh * 64 + d] * cv;
        }
        sr[i] = val;
    }
    __syncthreads();
    if (w < NKV) {
        int hh = w;
        float v0 = sr[hh * 64 + lane], v1 = sr[hh * 64 + 32 + lane];
        float ss = v0 * v0 + v1 * v1;
        #pragma unroll
        for (int o = 16; o; o >>= 1) ss += __shfl_xor_sync(0xffffffffu, ss, o);
        float sc = rsqrtf(ss / 64.f + 1e-6f) * 1.2f;
        Kb[hh * 64 + lane] = v0 * sc;
        Kb[hh * 64 + 32 + lane] = v1 * sc;
    }
    {
        Vb[tid] = Vb[tid] + gsm[tid >> 6] * ve[(size_t)t * (NKV * HD) + tid];
    }
}

// ---------------- flash attention (tf32 mma) with refine conv ----------------
__global__ void __launch_bounds__(256) k_flash(const float* __restrict__ QKV, const float* __restrict__ prev,
                        const float* __restrict__ rw, const float* __restrict__ alphap,
                        float* __restrict__ Y) {
    extern __shared__ float sm[];
    unsigned* Qs = (unsigned*)sm;          // 64*68 tf32
    unsigned* Ks = Qs + 64 * 68;           // 64*68 tf32
    unsigned* Vt = Ks + 64 * 68;           // 64*68 tf32, [d][key]
    float* Ss = (float*)(Vt + 64 * 68);    // 64*68 float, becomes tf32 P
    float* Ps = Ss + 64 * 68;              // 66*66
    float* mrow = Ps + 66 * 66;
    float* lrow = mrow + 64;
    float* crow = lrow + 64;
    int tid = threadIdx.x, lane = tid & 31, w = tid >> 5;
    int g = lane >> 2, t4 = lane & 3;
    int wm = w >> 1, wn = w & 1;
    int qt = blockIdx.x, h = blockIdx.y, b = blockIdx.z;
    int q0 = qt * 64, hk = h >> 2;
    float alpha = alphap[0];
    float w9[9];
    #pragma unroll
    for (int i = 0; i < 9; i++) w9[i] = rw[h * 9 + i];

    for (int idx = tid; idx < 64 * 64; idx += 256) {
        int r = idx >> 6, d = idx & 63;
        Qs[r * 68 + d] = f2tf(QKV[((size_t)(b * T) + q0 + r) * QKVW + h * 64 + d]);
    }
    if (tid < 64) { mrow[tid] = -INFINITY; lrow[tid] = 0.f; }
    float o[4][4];
    #pragma unroll
    for (int i = 0; i < 4; i++)
        #pragma unroll
        for (int j = 0; j < 4; j++) o[i][j] = 0.f;

    for (int kt = 0; kt <= qt; kt++) {
        int k0 = kt * 64;
        __syncthreads();
        for (int idx = tid; idx < 64 * 64; idx += 256) {
            int r = idx >> 6, d = idx & 63;
            size_t base = ((size_t)(b * T) + k0 + r) * QKVW;
            Ks[r * 68 + d] = f2tf(QKV[base + 1024 + hk * 64 + d]);
            Vt[d * 68 + r] = f2tf(QKV[base + 1280 + hk * 64 + d]);
        }
        for (int idx = tid; idx < 66 * 66; idx += 256) {
            int li = idx / 66, lj = idx - li * 66;
            int gi = q0 - 1 + li, gj = k0 - 1 + lj;
            float v = 0.f;
            if (gi >= 0 && gi < T && gj >= 0 && gj < T)
                v = prev[(((size_t)(b * NH) + h) * T + gi) * T + gj];
            Ps[idx] = v;
        }
        __syncthreads();
        // S = Q K^T
        float sacc[4][4];
        #pragma unroll
        for (int i = 0; i < 4; i++)
            #pragma unroll
            for (int j = 0; j < 4; j++) sacc[i][j] = 0.f;
        #pragma unroll
        for (int kk = 0; kk < 8; kk++) {
            unsigned a0 = Qs[(wm * 16 + g) * 68 + kk * 8 + t4];
            unsigned a1 = Qs[(wm * 16 + 8 + g) * 68 + kk * 8 + t4];
            unsigned a2 = Qs[(wm * 16 + g) * 68 + kk * 8 + 4 + t4];
            unsigned a3 = Qs[(wm * 16 + 8 + g) * 68 + kk * 8 + 4 + t4];
            #pragma unroll
            for (int nt = 0; nt < 4; nt++) {
                unsigned b0 = Ks[(wn * 32 + nt * 8 + g) * 68 + kk * 8 + t4];
                unsigned b1 = Ks[(wn * 32 + nt * 8 + g) * 68 + kk * 8 + 4 + t4];
                mma8(sacc[nt], a0, a1, a2, a3, b0, b1);
            }
        }
        // conv + mask + write S (float)
        #pragma unroll
        for (int nt = 0; nt < 4; nt++) {
            #pragma unroll
            for (int cc = 0; cc < 4; cc++) {
                int ri = wm * 16 + g + ((cc >= 2) ? 8 : 0);
                int cj = wn * 32 + nt * 8 + 2 * t4 + (cc & 1);
                float v = sacc[nt][cc] * 0.125f;
                float cv = 0.f;
                #pragma unroll
                for (int a = 0; a < 3; a++)
                    #pragma unroll
                    for (int bb = 0; bb < 3; bb++)
                        cv = fmaf(w9[a * 3 + bb], Ps[(ri + a) * 66 + cj + bb], cv);
                v += alpha * cv;
                if (k0 + cj > q0 + ri) v = -INFINITY;
                Ss[ri * 68 + cj] = v;
            }
        }
        __syncthreads();
        // online softmax: 4 threads per row
        {
            int row = tid >> 2, part = tid & 3;
            float* srow = Ss + row * 68 + part * 16;
            float rm = -INFINITY;
            #pragma unroll
            for (int j = 0; j < 16; j++) rm = fmaxf(rm, srow[j]);
            rm = fmaxf(rm, __shfl_xor_sync(0xffffffffu, rm, 1));
            rm = fmaxf(rm, __shfl_xor_sync(0xffffffffu, rm, 2));
            float mo = mrow[row];
            float nm = fmaxf(mo, rm);
            float sum = 0.f;
            unsigned* pu = (unsigned*)srow;
            #pragma unroll
            for (int j = 0; j < 16; j++) {
                float p = __expf(srow[j] - nm);
                sum += p;
                pu[j] = f2tf(p);
            }
            sum += __shfl_xor_sync(0xffffffffu, sum, 1);
            sum += __shfl_xor_sync(0xffffffffu, sum, 2);
            if (part == 0) {
                float corr = __expf(mo - nm);
                mrow[row] = nm;
                lrow[row] = lrow[row] * corr + sum;
                crow[row] = corr;
            }
        }
        __syncthreads();
        // rescale + O += P V
        float c0 = crow[wm * 16 + g], c1 = crow[wm * 16 + 8 + g];
        #pragma unroll
        for (int nt = 0; nt < 4; nt++) {
            o[nt][0] *= c0; o[nt][1] *= c0; o[nt][2] *= c1; o[nt][3] *= c1;
        }
        unsigned* Su = (unsigned*)Ss;
        #pragma unroll
        for (int kk = 0; kk < 8; kk++) {
            unsigned a0 = Su[(wm * 16 + g) * 68 + kk * 8 + t4];
            unsigned a1 = Su[(wm * 16 + 8 + g) * 68 + kk * 8 + t4];
            unsigned a2 = Su[(wm * 16 + g) * 68 + kk * 8 + 4 + t4];
            unsigned a3 = Su[(wm * 16 + 8 + g) * 68 + kk * 8 + 4 + t4];
            #pragma unroll
            for (int nt = 0; nt < 4; nt++) {
                unsigned b0 = Vt[(wn * 32 + nt * 8 + g) * 68 + kk * 8 + t4];
                unsigned b1 = Vt[(wn * 32 + nt * 8 + g) * 68 + kk * 8 + 4 + t4];
                mma8(o[nt], a0, a1, a2, a3, b0, b1);
            }
        }
    }
    {
        float inv0 = 1.f / lrow[wm * 16 + g];
        float inv1 = 1.f / lrow[wm * 16 + 8 + g];
        int r0 = q0 + wm * 16 + g;
        #pragma unroll
        for (int nt = 0; nt < 4; nt++) {
            int cj = wn * 32 + nt * 8 + 2 * t4;
            *(float2*)&Y[((size_t)(b * T) + r0) * C + h * 64 + cj] =
                make_float2(o[nt][0] * inv0, o[nt][1] * inv0);
            *(float2*)&Y[((size_t)(b * T) + r0 + 8) * C + h * 64 + cj] =
                make_float2(o[nt][2] * inv1, o[nt][3] * inv1);
        }
    }
}

// ---------------- 32-dim projection ----------------
__global__ void k_dot32(const float* __restrict__ X, const float* __restrict__ W,
                        float* __restrict__ OUT) {
    __shared__ float sx[8 * C];
    int t0 = blockIdx.x * 8;
    for (int i = threadIdx.x; i < 8 * C; i += 256) sx[i] = X[(size_t)t0 * C + i];
    __syncthreads();
    int tok = threadIdx.x >> 5, o = threadIdx.x & 31;
    const float4* wr = (const float4*)(W + (size_t)o * C);
    const float4* xr = (const float4*)(sx + tok * C);
    float s = 0.f;
    #pragma unroll 4
    for (int k = 0; k < C / 4; k++) {
        float4 a = xr[k], b = wr[k];
        s += a.x * b.x + a.y * b.y + a.z * b.z + a.w * b.w;
    }
    OUT[(size_t)(t0 + tok) * CADIM + o] = s;
}

// ---------------- ca channel conv + gelu ----------------
__global__ void k_caconv(const float* __restrict__ R, const float* __restrict__ cw,
                         float* __restrict__ OUT) {
    int b = blockIdx.y, t0 = blockIdx.x * 128;
    __shared__ float s[130 * 32];
    __shared__ float w[32 * 3];
    for (int i = threadIdx.x; i < 96; i += 256) w[i] = cw[i];
    for (int i = threadIdx.x; i < 130 * 32; i += 256) {
        int r = i >> 5, c = i & 31;
        int t = t0 - 1 + r;
        s[i] = (t >= 0 && t < T) ? R[((size_t)(b * T) + t) * CADIM + c] : 0.f;
    }
    __syncthreads();
    for (int i = threadIdx.x; i < 128 * 32; i += 256) {
        int r = i >> 5, c = i & 31;
        float h0 = s[(r + 1) * 32 + c];
        float cv = w[c * 3 + 0] * s[r * 32 + c] + w[c * 3 + 1] * h0 + w[c * 3 + 2] * s[(r + 2) * 32 + c];
        float v = h0 + 0.1f * cv;
        v = 0.5f * v * (1.f + erff(v * 0.70710678118f));
        OUT[((size_t)(b * T) + t0 + r) * CADIM + c] = v;
    }
}

// ---------------- x1 = x + attn*(1 + 0.1*tanh(cah @ ca_po^T)) ----------------
__global__ void k_x1(const float* __restrict__ x, const float* __restrict__ attn,
                     const float* __restrict__ cah, const float* __restrict__ capo,
                     float* __restrict__ X1) {
    int tg = blockIdx.x;
    __shared__ float h[16 * 32];
    __shared__ float po[256 * 33];
    int tid = threadIdx.x;
    for (int i = tid; i < 16 * 32; i += 256) h[i] = cah[(size_t)tg * 16 * 32 + i];
    for (int cc = 0; cc < 4; cc++) {
        int c0 = cc * 256;
        __syncthreads();
        for (int i = tid; i < 256 * 32; i += 256) po[(i >> 5) * 33 + (i & 31)] = capo[(size_t)c0 * 32 + i];
        __syncthreads();
        float wv[32];
        #pragma unroll
        for (int j = 0; j < 32; j++) wv[j] = po[tid * 33 + j];
        int c = c0 + tid;
        for (int tok = 0; tok < 16; tok++) {
            float ca = 0.f;
            #pragma unroll
            for (int j = 0; j < 32; j++) ca = fmaf(wv[j], h[tok * 32 + j], ca);
            size_t idx = ((size_t)tg * 16 + tok) * C + c;
            X1[idx] = x[idx] + attn[idx] * (1.f + 0.1f * tanhf(ca));
        }
    }
}

// ---------------- FFN depthwise conv, 4 fused iterations (reads HG stride FW) ----------------
__global__ void k_ffnconv(const float* __restrict__ Hin, const float* __restrict__ cw,
                          float* __restrict__ Hout) {
    int c0 = blockIdx.x * 32, t0 = blockIdx.y * 64, b = blockIdx.z;
    __shared__ float bufA[72 * 32];
    __shared__ float bufB[72 * 32];
    __shared__ float w[32 * 3];
    int tid = threadIdx.x;
    for (int i = tid; i < 96; i += 256) w[i] = cw[(size_t)c0 * 3 + i];
    for (int i = tid; i < 72 * 32; i += 256) {
        int r = i >> 5, c = i & 31;
        int t = t0 - 4 + r;
        bufA[i] = (t >= 0 && t < T) ? Hin[((size_t)(b * T) + t) * FW + c0 + c] : 0.f;
    }
    float* A = bufA;
    float* Bf = bufB;
    for (int it = 0; it < 4; it++) {
        __syncthreads();
        for (int i = tid; i < 72 * 32; i += 256) {
            int r = i >> 5, c = i & 31;
            int t = t0 - 4 + r;
            float v = 0.f;
            if (t >= 0 && t < T) {
                float am = (r > 0) ? A[(r - 1) * 32 + c] : 0.f;
                float a0 = A[i];
                float ap = (r < 71) ? A[(r + 1) * 32 + c] : 0.f;
                v = a0 + 0.1f * (w[c * 3] * am + w[c * 3 + 1] * a0 + w[c * 3 + 2] * ap);
            }
            Bf[i] = v;
        }
        float* tmp = A; A = Bf; Bf = tmp;
    }
    __syncthreads();
    for (int i = tid; i < 64 * 32; i += 256) {
        int r = i >> 5, c = i & 31;
        Hout[((size_t)(b * T) + t0 + r) * FFNH + c0 + c] = A[(r + 4) * 32 + c];
    }
}

// ---------------- vit head ----------------
__global__ void k_vitpost(const float* __restrict__ VR, const float* __restrict__ w2,
                          float* __restrict__ VIT) {
    int t = blockIdx.x * 256 + threadIdx.x;
    float s = 0.f;
    #pragma unroll
    for (int j = 0; j < 32; j++) {
        float v = VR[(size_t)t * 32 + j];
        v = 0.5f * v * (1.f + erff(v * 0.70710678118f));
        s += v * w2[j];
    }
    VIT[t] = 1.f / (1.f + __expf(-s));
}

__global__ void k_vsmooth(const float* __restrict__ VIT, float* __restrict__ VITF) {
    int b = blockIdx.x;
    for (int t = threadIdx.x; t < T; t += 256) {
        float v = VIT[b * T + t];
        float s = 0.f;
        #pragma unroll
        for (int d = -2; d <= 2; d++) {
            int tt = t + d;
            if (tt >= 0 && tt < T) s += VIT[b * T + tt];
        }
        s *= 0.2f;
        float f = 0.7f * v + 0.3f * s;
        VITF[b * T + t] = (f > 0.3f) ? f : 0.1f * f;
    }
}

// ---------------- final combine ----------------
__global__ void k_final(const float* __restrict__ x1, const float* __restrict__ mlp,
                        const float* __restrict__ HG, const float* __restrict__ cah,
                        const float* __restrict__ capo, const float* __restrict__ vitf,
                        float* __restrict__ out) {
    int tg = blockIdx.x;
    __shared__ float h[16 * 32];
    __shared__ float po[256 * 33];
    __shared__ float sv[16];
    int tid = threadIdx.x;
    for (int i = tid; i < 16 * 32; i += 256) h[i] = cah[(size_t)tg * 16 * 32 + i];
    if (tid < 16) sv[tid] = vitf[tg * 16 + tid];
    for (int cc = 0; cc < 4; cc++) {
        int c0 = cc * 256;
        __syncthreads();
        for (int i = tid; i < 256 * 32; i += 256) po[(i >> 5) * 33 + (i & 31)] = capo[(size_t)c0 * 32 + i];
        __syncthreads();
        float wv[32];
        #pragma unroll
        for (int j = 0; j < 32; j++) wv[j] = po[tid * 33 + j];
        int c = c0 + tid;
        for (int tok = 0; tok < 16; tok++) {
            float ca = 0.f;
            #pragma unroll
            for (int j = 0; j < 32; j++) ca = fmaf(wv[j], h[tok * 32 + j], ca);
            size_t idx = ((size_t)tg * 16 + tok) * C + c;
            float gate = HG[((size_t)tg * 16 + tok) * FW + 4096 + c];
            float m = mlp[idx] * gate * (1.f + 0.1f * tanhf(ca)) * sv[tok];
            out[idx] = x1[idx] + m;
        }
    }
}

// ---------------- host ----------------
extern "C" void kernel_launch(void* const* d_in, const int* in_sizes, int n_in,
                              void* d_out, int out_size) {
    const float* x        = (const float*)d_in[0];
    const float* ve       = (const float*)d_in[1];
    const float* cosb     = (const float*)d_in[2];
    const float* sinb     = (const float*)d_in[3];
    const float* prev     = (const float*)d_in[4];
    const float* w_q      = (const float*)d_in[5];
    const float* w_k      = (const float*)d_in[6];
    const float* w_v      = (const float*)d_in[7];
    const float* w_o      = (const float*)d_in[8];
    const float* w_veg    = (const float*)d_in[9];
    const float* refine_w = (const float*)d_in[10];
    const float* alpha    = (const float*)d_in[11];
    const float* ca_pi    = (const float*)d_in[12];
    const float* ca_cw    = (const float*)d_in[13];
    const float* ca_po    = (const float*)d_in[14];
    const float* ffn_in   = (const float*)d_in[15];
    const float* ffn_cw   = (const float*)d_in[16];
    const float* ffn_out  = (const float*)d_in[17];
    const float* ffn_gate = (const float*)d_in[18];
    const float* vit_w1   = (const float*)d_in[19];
    const float* vit_w2   = (const float*)d_in[20];
    float* out = (float*)d_out;

    float *XN, *QKV, *WQKV, *Yp, *ATT, *X1, *XM, *WF, *HG, *H2, *MLP, *CR, *CA1, *CA2, *VR, *VIT, *VITF;
    cudaGetSymbolAddress((void**)&XN, g_XN);
    cudaGetSymbolAddress((void**)&QKV, g_QKV);
    cudaGetSymbolAddress((void**)&WQKV, g_WQKV);
    cudaGetSymbolAddress((void**)&Yp, g_Y);
    cudaGetSymbolAddress((void**)&ATT, g_ATT);
    cudaGetSymbolAddress((void**)&X1, g_X1);
    cudaGetSymbolAddress((void**)&XM, g_XM);
    cudaGetSymbolAddress((void**)&WF, g_WF);
    cudaGetSymbolAddress((void**)&HG, g_HG);
    cudaGetSymbolAddress((void**)&H2, g_H2);
    cudaGetSymbolAddress((void**)&MLP, g_MLP);
    cudaGetSymbolAddress((void**)&CR, g_CR);
    cudaGetSymbolAddress((void**)&CA1, g_CA1);
    cudaGetSymbolAddress((void**)&CA2, g_CA2);
    cudaGetSymbolAddress((void**)&VR, g_VR);
    cudaGetSymbolAddress((void**)&VIT, g_VIT);
    cudaGetSymbolAddress((void**)&VITF, g_VITF);

    // concat weights (D2D, cheap)
    cudaMemcpyAsync(WQKV,                  w_q, (size_t)1024 * C * 4, cudaMemcpyDeviceToDevice);
    cudaMemcpyAsync(WQKV + 1024 * C,       w_k, (size_t)256 * C * 4, cudaMemcpyDeviceToDevice);
    cudaMemcpyAsync(WQKV + 1280 * C,       w_v, (size_t)256 * C * 4, cudaMemcpyDeviceToDevice);
    cudaMemcpyAsync(WF,                    ffn_in,   (size_t)4096 * C * 4, cudaMemcpyDeviceToDevice);
    cudaMemcpyAsync(WF + (size_t)4096 * C, ffn_gate, (size_t)1024 * C * 4, cudaMemcpyDeviceToDevice);

    k_rmsnorm<<<BT, 256>>>(x, XN);
    k_mgemm<0><<<dim3(QKVW / 128, BT / 128), 256>>>(XN, WQKV, QKV, BT, QKVW, C);
    k_ropegate<<<BT, 256>>>(QKV, XN, ve, cosb, sinb, w_veg);

    int smemf = (4 * 64 * 68 + 66 * 66 + 3 * 64) * (int)sizeof(float);
    cudaFuncSetAttribute(k_flash, cudaFuncAttributeMaxDynamicSharedMemorySize, smemf);
    k_flash<<<dim3(T / 64, NH, BB), 256, smemf>>>(QKV, prev, refine_w, alpha, Yp);

    k_mgemm<0><<<dim3(C / 128, BT / 128), 256>>>(Yp, w_o, ATT, BT, C, C);

    k_dot32<<<BT / 8, 256>>>(x, ca_pi, CR);
    k_caconv<<<dim3(T / 128, BB), 256>>>(CR, ca_cw, CA1);
    k_x1<<<BT / 16, 256>>>(x, ATT, CA1, ca_po, X1);

    k_rmsnorm<<<BT, 256>>>(X1, XM);
    k_mgemm<3><<<dim3(FW / 128, BT / 128), 256>>>(XM, WF, HG, BT, FW, C);
    k_ffnconv<<<dim3(FFNH / 32, T / 64, BB), 256>>>(HG, ffn_cw, H2);
    k_mgemm<0><<<dim3(C / 128, BT / 128), 256>>>(H2, ffn_out, MLP, BT, C, FFNH);

    k_dot32<<<BT / 8, 256>>>(X1, ca_pi, CR);
    k_caconv<<<dim3(T / 128, BB), 256>>>(CR, ca_cw, CA2);
    k_dot32<<<BT / 8, 256>>>(X1, vit_w1, VR);
    k_vitpost<<<BT / 256, 256>>>(VR, vit_w2, VIT);
    k_vsmooth<<<BB, 256>>>(VIT, VITF);

    k_final<<<BT / 16, 256>>>(X1, MLP, HG, CA2, ca_po, VITF, out);
}

// round 3
// speedup vs baseline: 2.2902x; 1.1836x over previous
#include <cuda_runtime.h>
#include <math.h>

#define BB 4
#define T 1024
#define C 1024
#define BT (BB*T)
#define NH 16
#define NKV 4
#define HD 64
#define FFNH 4096
#define CADIM 32
#define VECH 12
#define QKVW 1536
#define FW 5120

// ---------------- scratch ----------------
__device__ float g_XN[BT*C];
__device__ float g_QKV[BT*QKVW];
__device__ float g_WQKV[QKVW*C];
__device__ float g_Y[BT*C];
__device__ float g_ATT[BT*C];
__device__ float g_X1[BT*C];
__device__ float g_XM[BT*C];
__device__ float g_WF[FW*C];
__device__ float g_HG[(size_t)BT*FW];
__device__ float g_H2[(size_t)BT*FFNH];
__device__ float g_MLP[BT*C];
__device__ float g_CR[BT*CADIM];
__device__ float g_CA1[BT*CADIM];
__device__ float g_CA2[BT*CADIM];
__device__ float g_VR[BT*CADIM];
__device__ float g_VIT[BT];
__device__ float g_VITF[BT];

// ---------------- mma / cp.async helpers ----------------
__device__ __forceinline__ void mma8(float* c, unsigned a0, unsigned a1, unsigned a2, unsigned a3,
                                     unsigned b0, unsigned b1) {
    asm("mma.sync.aligned.m16n8k8.row.col.f32.tf32.tf32.f32 "
        "{%0,%1,%2,%3},{%4,%5,%6,%7},{%8,%9},{%0,%1,%2,%3};"
        : "+f"(c[0]), "+f"(c[1]), "+f"(c[2]), "+f"(c[3])
        : "r"(a0), "r"(a1), "r"(a2), "r"(a3), "r"(b0), "r"(b1));
}
__device__ __forceinline__ void cpa16(void* s, const void* g) {
    unsigned sa = (unsigned)__cvta_generic_to_shared(s);
    asm volatile("cp.async.cg.shared.global [%0], [%1], 16;\n" :: "r"(sa), "l"(g));
}
#define CPCOMMIT() asm volatile("cp.async.commit_group;\n")
template<int N> __device__ __forceinline__ void cpwait() {
    asm volatile("cp.async.wait_group %0;\n" :: "n"(N));
}
__device__ __forceinline__ unsigned fbits(float x) { return __float_as_uint(x); }

// ---------------- rmsnorm ----------------
__global__ void k_rmsnorm(const float* __restrict__ x, float* __restrict__ y) {
    int t = blockIdx.x;
    __shared__ float sx[C];
    __shared__ float red[8];
    const float* xr = x + (size_t)t * C;
    float ss = 0.f;
    for (int i = threadIdx.x; i < C; i += 256) { float v = xr[i]; sx[i] = v; ss += v * v; }
    #pragma unroll
    for (int o = 16; o; o >>= 1) ss += __shfl_xor_sync(0xffffffffu, ss, o);
    if ((threadIdx.x & 31) == 0) red[threadIdx.x >> 5] = ss;
    __syncthreads();
    if (threadIdx.x < 8) {
        float v = red[threadIdx.x];
        #pragma unroll
        for (int o = 4; o; o >>= 1) v += __shfl_xor_sync(0xffu, v, o);
        if (threadIdx.x == 0) red[0] = v;
    }
    __syncthreads();
    float sc = rsqrtf(red[0] / (float)C + 1e-6f);
    float* yr = y + (size_t)t * C;
    for (int i = threadIdx.x; i < C; i += 256) yr[i] = sx[i] * sc;
}

// ---------------- tf32 MMA GEMM, cp.async 2-stage, BK=32 ----------------
// C[M,N] = A[M,K] @ W[N,K]^T. EPI: 0 none, 3 = (col<4096 relu^2 else sigmoid)
template<int EPI>
__global__ void __launch_bounds__(256) k_mgemm(const float* __restrict__ A, const float* __restrict__ W,
                                               float* __restrict__ Cout, int M, int N, int K) {
    __shared__ float As[2][128][36];
    __shared__ float Bs[2][128][36];
    const int tid = threadIdx.x, lane = tid & 31, w = tid >> 5;
    const int g = lane >> 2, t4 = lane & 3;
    const int wm = w >> 1, wn = w & 1;
    const int bm = blockIdx.y * 128, bn = blockIdx.x * 128;
    const int r = tid >> 3, c4 = (tid & 7) * 4;
    const float* Ap = A + (size_t)bm * K;
    const float* Wp = W + (size_t)bn * K;

    float acc[2][8][4];
    #pragma unroll
    for (int i = 0; i < 2; i++)
        #pragma unroll
        for (int j = 0; j < 8; j++)
            #pragma unroll
            for (int p = 0; p < 4; p++) acc[i][j][p] = 0.f;

    #pragma unroll
    for (int i = 0; i < 4; i++) {
        cpa16(&As[0][i * 32 + r][c4], Ap + (size_t)(i * 32 + r) * K + c4);
        cpa16(&Bs[0][i * 32 + r][c4], Wp + (size_t)(i * 32 + r) * K + c4);
    }
    CPCOMMIT();
    #pragma unroll
    for (int i = 0; i < 4; i++) {
        cpa16(&As[1][i * 32 + r][c4], Ap + (size_t)(i * 32 + r) * K + 32 + c4);
        cpa16(&Bs[1][i * 32 + r][c4], Wp + (size_t)(i * 32 + r) * K + 32 + c4);
    }
    CPCOMMIT();
    cpwait<1>();
    __syncthreads();

    const int nit = K / 32;
    for (int it = 0; it < nit; it++) {
        int cur = it & 1;
        #pragma unroll
        for (int kk = 0; kk < 4; kk++) {
            unsigned a[2][4];
            #pragma unroll
            for (int mt = 0; mt < 2; mt++) {
                int r0 = wm * 32 + mt * 16;
                a[mt][0] = fbits(As[cur][r0 + g][kk * 8 + t4]);
                a[mt][1] = fbits(As[cur][r0 + 8 + g][kk * 8 + t4]);
                a[mt][2] = fbits(As[cur][r0 + g][kk * 8 + 4 + t4]);
                a[mt][3] = fbits(As[cur][r0 + 8 + g][kk * 8 + 4 + t4]);
            }
            #pragma unroll
            for (int nt = 0; nt < 8; nt++) {
                int c0 = wn * 64 + nt * 8;
                unsigned b0 = fbits(Bs[cur][c0 + g][kk * 8 + t4]);
                unsigned b1 = fbits(Bs[cur][c0 + g][kk * 8 + 4 + t4]);
                mma8(acc[0][nt], a[0][0], a[0][1], a[0][2], a[0][3], b0, b1);
                mma8(acc[1][nt], a[1][0], a[1][1], a[1][2], a[1][3], b0, b1);
            }
        }
        __syncthreads();
        if (it + 2 < nit) {
            int kn = (it + 2) * 32;
            #pragma unroll
            for (int i = 0; i < 4; i++) {
                cpa16(&As[cur][i * 32 + r][c4], Ap + (size_t)(i * 32 + r) * K + kn + c4);
                cpa16(&Bs[cur][i * 32 + r][c4], Wp + (size_t)(i * 32 + r) * K + kn + c4);
            }
        }
        CPCOMMIT();
        cpwait<1>();
        __syncthreads();
    }

    #pragma unroll
    for (int mt = 0; mt < 2; mt++) {
        #pragma unroll
        for (int nt = 0; nt < 8; nt++) {
            int row = bm + wm * 32 + mt * 16 + g;
            int col = bn + wn * 64 + nt * 8 + 2 * t4;
            float v[4];
            #pragma unroll
            for (int p = 0; p < 4; p++) {
                float x = acc[mt][nt][p];
                if (EPI == 3) {
                    if (col < 4096) { float rr = fmaxf(x, 0.f); x = rr * rr; }
                    else x = 1.f / (1.f + __expf(-x));
                }
                v[p] = x;
            }
            *(float2*)&Cout[(size_t)row * N + col] = make_float2(v[0], v[1]);
            *(float2*)&Cout[(size_t)(row + 8) * N + col] = make_float2(v[2], v[3]);
        }
    }
}

// ---------------- gate + rope + per-head rmsnorm (fused QKV layout) ----------------
__global__ void k_ropegate(float* __restrict__ QKV, const float* __restrict__ XN,
                           const float* __restrict__ ve, const float* __restrict__ cosb,
                           const float* __restrict__ sinb, const float* __restrict__ wveg) {
    int t = blockIdx.x;
    int tt = t & (T - 1);
    __shared__ float sq[NH * HD];
    __shared__ float sr[NH * HD];
    __shared__ float gsm[NKV];
    int tid = threadIdx.x;
    float* Qb = QKV + (size_t)t * QKVW;
    float* Kb = Qb + 1024;
    float* Vb = Qb + 1280;
    if (tid < NKV) {
        float s = 0.f;
        #pragma unroll
        for (int j = 0; j < VECH; j++) s += XN[(size_t)t * C + j] * wveg[tid * VECH + j];
        gsm[tid] = 3.f / (1.f + __expf(-s));
    }
    for (int i = tid; i < NH * HD; i += 256) sq[i] = Qb[i];
    __syncthreads();
    for (int i = tid; i < NH * HD; i += 256) {
        int hh = i >> 6, d = i & 63;
        float val;
        if (d < 32) {
            float cv = cosb[tt * 32 + d], sv = sinb[tt * 32 + d];
            val = sq[hh * 64 + d] * cv + sq[hh * 64 + d + 32] * sv;
        } else {
            int d2 = d - 32;
            float cv = cosb[tt * 32 + d2], sv = sinb[tt * 32 + d2];
            val = -sq[hh * 64 + d2] * sv + sq[hh * 64 + d] * cv;
        }
        sr[i] = val;
    }
    __syncthreads();
    int w = tid >> 5, lane = tid & 31;
    for (int hh = w; hh < NH; hh += 8) {
        float v0 = sr[hh * 64 + lane], v1 = sr[hh * 64 + 32 + lane];
        float ss = v0 * v0 + v1 * v1;
        #pragma unroll
        for (int o = 16; o; o >>= 1) ss += __shfl_xor_sync(0xffffffffu, ss, o);
        float sc = rsqrtf(ss / 64.f + 1e-6f) * 1.2f;
        Qb[hh * 64 + lane] = v0 * sc;
        Qb[hh * 64 + 32 + lane] = v1 * sc;
    }
    __syncthreads();
    for (int i = tid; i < NKV * HD; i += 256) sq[i] = Kb[i];
    __syncthreads();
    for (int i = tid; i < NKV * HD; i += 256) {
        int hh = i >> 6, d = i & 63;
        float val;
        if (d < 32) {
            float cv = cosb[tt * 32 + d], sv = sinb[tt * 32 + d];
            val = sq[hh * 64 + d] * cv + sq[hh * 64 + d + 32] * sv;
        } else {
            int d2 = d - 32;
            float cv = cosb[tt * 32 + d2], sv = sinb[tt * 32 + d2];
            val = -sq[hh * 64 + d2] * sv + sq[hh * 64 + d] * cv;
        }
        sr[i] = val;
    }
    __syncthreads();
    if (w < NKV) {
        int hh = w;
        float v0 = sr[hh * 64 + lane], v1 = sr[hh * 64 + 32 + lane];
        float ss = v0 * v0 + v1 * v1;
        #pragma unroll
        for (int o = 16; o; o >>= 1) ss += __shfl_xor_sync(0xffffffffu, ss, o);
        float sc = rsqrtf(ss / 64.f + 1e-6f) * 1.2f;
        Kb[hh * 64 + lane] = v0 * sc;
        Kb[hh * 64 + 32 + lane] = v1 * sc;
    }
    {
        Vb[tid] = Vb[tid] + gsm[tid >> 6] * ve[(size_t)t * (NKV * HD) + tid];
    }
}

// ---------------- flash attention (tf32 raw-bit mma) with refine conv ----------------
// smem: Qs(64x68) | KS(64x68, aliased S/P) | Vt(64x68) | Ps(66x66) | stats
__global__ void __launch_bounds__(256) k_flash(const float* __restrict__ QKV, const float* __restrict__ prev,
                        const float* __restrict__ rw, const float* __restrict__ alphap,
                        float* __restrict__ Y) {
    extern __shared__ float sm[];
    float* Qs = sm;
    float* KS = Qs + 64 * 68;
    float* Vt = KS + 64 * 68;
    float* Ps = Vt + 64 * 68;
    float* mrow = Ps + 66 * 66;
    float* lrow = mrow + 64;
    float* crow = lrow + 64;
    int tid = threadIdx.x, lane = tid & 31, w = tid >> 5;
    int g = lane >> 2, t4 = lane & 3;
    int wm = w >> 1, wn = w & 1;
    int qt = blockIdx.x, h = blockIdx.y, b = blockIdx.z;
    int q0 = qt * 64, hk = h >> 2;
    float alpha = alphap[0];
    float w9[9];
    #pragma unroll
    for (int i = 0; i < 9; i++) w9[i] = rw[h * 9 + i];

    for (int i = tid; i < 1024; i += 256) {
        int rr = i >> 4, d4 = (i & 15) << 2;
        *(float4*)&Qs[rr * 68 + d4] =
            *(const float4*)&QKV[((size_t)(b * T) + q0 + rr) * QKVW + h * 64 + d4];
    }
    if (tid < 64) { mrow[tid] = -INFINITY; lrow[tid] = 0.f; }
    float o[4][4];
    #pragma unroll
    for (int i = 0; i < 4; i++)
        #pragma unroll
        for (int j = 0; j < 4; j++) o[i][j] = 0.f;

    for (int kt = 0; kt <= qt; kt++) {
        int k0 = kt * 64;
        __syncthreads();
        for (int i = tid; i < 1024; i += 256) {
            int rr = i >> 4, d4 = (i & 15) << 2;
            const float* base = &QKV[((size_t)(b * T) + k0 + rr) * QKVW];
            *(float4*)&KS[rr * 68 + d4] = *(const float4*)&base[1024 + hk * 64 + d4];
            float4 v = *(const float4*)&base[1280 + hk * 64 + d4];
            Vt[(d4 + 0) * 68 + rr] = v.x;
            Vt[(d4 + 1) * 68 + rr] = v.y;
            Vt[(d4 + 2) * 68 + rr] = v.z;
            Vt[(d4 + 3) * 68 + rr] = v.w;
        }
        for (int idx = tid; idx < 66 * 66; idx += 256) {
            int li = idx / 66, lj = idx - li * 66;
            int gi = q0 - 1 + li, gj = k0 - 1 + lj;
            float v = 0.f;
            if (gi >= 0 && gi < T && gj >= 0 && gj < T)
                v = prev[(((size_t)(b * NH) + h) * T + gi) * T + gj];
            Ps[idx] = v;
        }
        __syncthreads();
        // S = Q K^T
        float sacc[4][4];
        #pragma unroll
        for (int i = 0; i < 4; i++)
            #pragma unroll
            for (int j = 0; j < 4; j++) sacc[i][j] = 0.f;
        #pragma unroll
        for (int kk = 0; kk < 8; kk++) {
            unsigned a0 = fbits(Qs[(wm * 16 + g) * 68 + kk * 8 + t4]);
            unsigned a1 = fbits(Qs[(wm * 16 + 8 + g) * 68 + kk * 8 + t4]);
            unsigned a2 = fbits(Qs[(wm * 16 + g) * 68 + kk * 8 + 4 + t4]);
            unsigned a3 = fbits(Qs[(wm * 16 + 8 + g) * 68 + kk * 8 + 4 + t4]);
            #pragma unroll
            for (int nt = 0; nt < 4; nt++) {
                unsigned b0 = fbits(KS[(wn * 32 + nt * 8 + g) * 68 + kk * 8 + t4]);
                unsigned b1 = fbits(KS[(wn * 32 + nt * 8 + g) * 68 + kk * 8 + 4 + t4]);
                mma8(sacc[nt], a0, a1, a2, a3, b0, b1);
            }
        }
        __syncthreads();  // all warps done reading K before S overwrites it
        // conv + mask; write S into KS
        #pragma unroll
        for (int nt = 0; nt < 4; nt++) {
            #pragma unroll
            for (int rg = 0; rg < 2; rg++) {
                int ri = wm * 16 + g + rg * 8;
                int cj = wn * 32 + nt * 8 + 2 * t4;
                float p[3][4];
                #pragma unroll
                for (int a = 0; a < 3; a++) {
                    float2 x0 = *(float2*)&Ps[(ri + a) * 66 + cj];
                    float2 x1 = *(float2*)&Ps[(ri + a) * 66 + cj + 2];
                    p[a][0] = x0.x; p[a][1] = x0.y; p[a][2] = x1.x; p[a][3] = x1.y;
                }
                float cv0 = 0.f, cv1 = 0.f;
                #pragma unroll
                for (int a = 0; a < 3; a++)
                    #pragma unroll
                    for (int bb = 0; bb < 3; bb++) {
                        cv0 = fmaf(w9[a * 3 + bb], p[a][bb], cv0);
                        cv1 = fmaf(w9[a * 3 + bb], p[a][bb + 1], cv1);
                    }
                float v0 = sacc[nt][rg * 2 + 0] * 0.125f + alpha * cv0;
                float v1 = sacc[nt][rg * 2 + 1] * 0.125f + alpha * cv1;
                if (k0 + cj > q0 + ri) v0 = -INFINITY;
                if (k0 + cj + 1 > q0 + ri) v1 = -INFINITY;
                KS[ri * 68 + cj] = v0;
                KS[ri * 68 + cj + 1] = v1;
            }
        }
        __syncthreads();
        // online softmax: 4 threads per row
        {
            int row = tid >> 2, part = tid & 3;
            float* srow = KS + row * 68 + part * 16;
            float rm = -INFINITY;
            #pragma unroll
            for (int j = 0; j < 16; j++) rm = fmaxf(rm, srow[j]);
            rm = fmaxf(rm, __shfl_xor_sync(0xffffffffu, rm, 1));
            rm = fmaxf(rm, __shfl_xor_sync(0xffffffffu, rm, 2));
            float mo = mrow[row];
            float nm = fmaxf(mo, rm);
            float sum = 0.f;
            #pragma unroll
            for (int j = 0; j < 16; j++) {
                float pv = __expf(srow[j] - nm);
                sum += pv;
                srow[j] = pv;
            }
            sum += __shfl_xor_sync(0xffffffffu, sum, 1);
            sum += __shfl_xor_sync(0xffffffffu, sum, 2);
            if (part == 0) {
                float corr = __expf(mo - nm);
                mrow[row] = nm;
                lrow[row] = lrow[row] * corr + sum;
                crow[row] = corr;
            }
        }
        __syncthreads();
        // rescale + O += P V
        float c0 = crow[wm * 16 + g], c1 = crow[wm * 16 + 8 + g];
        #pragma unroll
        for (int nt = 0; nt < 4; nt++) {
            o[nt][0] *= c0; o[nt][1] *= c0; o[nt][2] *= c1; o[nt][3] *= c1;
        }
        #pragma unroll
        for (int kk = 0; kk < 8; kk++) {
            unsigned a0 = fbits(KS[(wm * 16 + g) * 68 + kk * 8 + t4]);
            unsigned a1 = fbits(KS[(wm * 16 + 8 + g) * 68 + kk * 8 + t4]);
            unsigned a2 = fbits(KS[(wm * 16 + g) * 68 + kk * 8 + 4 + t4]);
            unsigned a3 = fbits(KS[(wm * 16 + 8 + g) * 68 + kk * 8 + 4 + t4]);
            #pragma unroll
            for (int nt = 0; nt < 4; nt++) {
                unsigned b0 = fbits(Vt[(wn * 32 + nt * 8 + g) * 68 + kk * 8 + t4]);
                unsigned b1 = fbits(Vt[(wn * 32 + nt * 8 + g) * 68 + kk * 8 + 4 + t4]);
                mma8(o[nt], a0, a1, a2, a3, b0, b1);
            }
        }
    }
    {
        float inv0 = 1.f / lrow[wm * 16 + g];
        float inv1 = 1.f / lrow[wm * 16 + 8 + g];
        int r0 = q0 + wm * 16 + g;
        #pragma unroll
        for (int nt = 0; nt < 4; nt++) {
            int cj = wn * 32 + nt * 8 + 2 * t4;
            *(float2*)&Y[((size_t)(b * T) + r0) * C + h * 64 + cj] =
                make_float2(o[nt][0] * inv0, o[nt][1] * inv0);
            *(float2*)&Y[((size_t)(b * T) + r0 + 8) * C + h * 64 + cj] =
                make_float2(o[nt][2] * inv1, o[nt][3] * inv1);
        }
    }
}

// ---------------- 32-dim projection ----------------
__global__ void k_dot32(const float* __restrict__ X, const float* __restrict__ W,
                        float* __restrict__ OUT) {
    __shared__ float sx[8 * C];
    int t0 = blockIdx.x * 8;
    for (int i = threadIdx.x; i < 8 * C; i += 256) sx[i] = X[(size_t)t0 * C + i];
    __syncthreads();
    int tok = threadIdx.x >> 5, o = threadIdx.x & 31;
    const float4* wr = (const float4*)(W + (size_t)o * C);
    const float4* xr = (const float4*)(sx + tok * C);
    float s = 0.f;
    #pragma unroll 4
    for (int k = 0; k < C / 4; k++) {
        float4 a = xr[k], b = wr[k];
        s += a.x * b.x + a.y * b.y + a.z * b.z + a.w * b.w;
    }
    OUT[(size_t)(t0 + tok) * CADIM + o] = s;
}

// ---------------- ca channel conv + gelu ----------------
__global__ void k_caconv(const float* __restrict__ R, const float* __restrict__ cw,
                         float* __restrict__ OUT) {
    int b = blockIdx.y, t0 = blockIdx.x * 128;
    __shared__ float s[130 * 32];
    __shared__ float w[32 * 3];
    for (int i = threadIdx.x; i < 96; i += 256) w[i] = cw[i];
    for (int i = threadIdx.x; i < 130 * 32; i += 256) {
        int r = i >> 5, c = i & 31;
        int t = t0 - 1 + r;
        s[i] = (t >= 0 && t < T) ? R[((size_t)(b * T) + t) * CADIM + c] : 0.f;
    }
    __syncthreads();
    for (int i = threadIdx.x; i < 128 * 32; i += 256) {
        int r = i >> 5, c = i & 31;
        float h0 = s[(r + 1) * 32 + c];
        float cv = w[c * 3 + 0] * s[r * 32 + c] + w[c * 3 + 1] * h0 + w[c * 3 + 2] * s[(r + 2) * 32 + c];
        float v = h0 + 0.1f * cv;
        v = 0.5f * v * (1.f + erff(v * 0.70710678118f));
        OUT[((size_t)(b * T) + t0 + r) * CADIM + c] = v;
    }
}

// ---------------- x1 = x + attn*(1 + 0.1*tanh(cah @ ca_po^T)) ----------------
__global__ void k_x1(const float* __restrict__ x, const float* __restrict__ attn,
                     const float* __restrict__ cah, const float* __restrict__ capo,
                     float* __restrict__ X1) {
    int tg = blockIdx.x;
    __shared__ float h[16 * 32];
    __shared__ float po[256 * 33];
    int tid = threadIdx.x;
    for (int i = tid; i < 16 * 32; i += 256) h[i] = cah[(size_t)tg * 16 * 32 + i];
    for (int cc = 0; cc < 4; cc++) {
        int c0 = cc * 256;
        __syncthreads();
        for (int i = tid; i < 256 * 32; i += 256) po[(i >> 5) * 33 + (i & 31)] = capo[(size_t)c0 * 32 + i];
        __syncthreads();
        float wv[32];
        #pragma unroll
        for (int j = 0; j < 32; j++) wv[j] = po[tid * 33 + j];
        int c = c0 + tid;
        for (int tok = 0; tok < 16; tok++) {
            float ca = 0.f;
            #pragma unroll
            for (int j = 0; j < 32; j++) ca = fmaf(wv[j], h[tok * 32 + j], ca);
            size_t idx = ((size_t)tg * 16 + tok) * C + c;
            X1[idx] = x[idx] + attn[idx] * (1.f + 0.1f * tanhf(ca));
        }
    }
}

// ---------------- FFN depthwise conv, 4 fused iterations ----------------
__global__ void k_ffnconv(const float* __restrict__ Hin, const float* __restrict__ cw,
                          float* __restrict__ Hout) {
    int c0 = blockIdx.x * 32, t0 = blockIdx.y * 64, b = blockIdx.z;
    __shared__ float bufA[72 * 32];
    __shared__ float bufB[72 * 32];
    __shared__ float w[32 * 3];
    int tid = threadIdx.x;
    for (int i = tid; i < 96; i += 256) w[i] = cw[(size_t)c0 * 3 + i];
    for (int i = tid; i < 72 * 32; i += 256) {
        int r = i >> 5, c = i & 31;
        int t = t0 - 4 + r;
        bufA[i] = (t >= 0 && t < T) ? Hin[((size_t)(b * T) + t) * FW + c0 + c] : 0.f;
    }
    float* A = bufA;
    float* Bf = bufB;
    for (int it = 0; it < 4; it++) {
        __syncthreads();
        for (int i = tid; i < 72 * 32; i += 256) {
            int r = i >> 5, c = i & 31;
            int t = t0 - 4 + r;
            float v = 0.f;
            if (t >= 0 && t < T) {
                float am = (r > 0) ? A[(r - 1) * 32 + c] : 0.f;
                float a0 = A[i];
                float ap = (r < 71) ? A[(r + 1) * 32 + c] : 0.f;
                v = a0 + 0.1f * (w[c * 3] * am + w[c * 3 + 1] * a0 + w[c * 3 + 2] * ap);
            }
            Bf[i] = v;
        }
        float* tmp = A; A = Bf; Bf = tmp;
    }
    __syncthreads();
    for (int i = tid; i < 64 * 32; i += 256) {
        int r = i >> 5, c = i & 31;
        Hout[((size_t)(b * T) + t0 + r) * FFNH + c0 + c] = A[(r + 4) * 32 + c];
    }
}

// ---------------- vit head ----------------
__global__ void k_vitpost(const float* __restrict__ VR, const float* __restrict__ w2,
                          float* __restrict__ VIT) {
    int t = blockIdx.x * 256 + threadIdx.x;
    float s = 0.f;
    #pragma unroll
    for (int j = 0; j < 32; j++) {
        float v = VR[(size_t)t * 32 + j];
        v = 0.5f * v * (1.f + erff(v * 0.70710678118f));
        s += v * w2[j];
    }
    VIT[t] = 1.f / (1.f + __expf(-s));
}

__global__ void k_vsmooth(const float* __restrict__ VIT, float* __restrict__ VITF) {
    int b = blockIdx.x;
    for (int t = threadIdx.x; t < T; t += 256) {
        float v = VIT[b * T + t];
        float s = 0.f;
        #pragma unroll
        for (int d = -2; d <= 2; d++) {
            int tt = t + d;
            if (tt >= 0 && tt < T) s += VIT[b * T + tt];
        }
        s *= 0.2f;
        float f = 0.7f * v + 0.3f * s;
        VITF[b * T + t] = (f > 0.3f) ? f : 0.1f * f;
    }
}

// ---------------- final combine ----------------
__global__ void k_final(const float* __restrict__ x1, const float* __restrict__ mlp,
                        const float* __restrict__ HG, const float* __restrict__ cah,
                        const float* __restrict__ capo, const float* __restrict__ vitf,
                        float* __restrict__ out) {
    int tg = blockIdx.x;
    __shared__ float h[16 * 32];
    __shared__ float po[256 * 33];
    __shared__ float sv[16];
    int tid = threadIdx.x;
    for (int i = tid; i < 16 * 32; i += 256) h[i] = cah[(size_t)tg * 16 * 32 + i];
    if (tid < 16) sv[tid] = vitf[tg * 16 + tid];
    for (int cc = 0; cc < 4; cc++) {
        int c0 = cc * 256;
        __syncthreads();
        for (int i = tid; i < 256 * 32; i += 256) po[(i >> 5) * 33 + (i & 31)] = capo[(size_t)c0 * 32 + i];
        __syncthreads();
        float wv[32];
        #pragma unroll
        for (int j = 0; j < 32; j++) wv[j] = po[tid * 33 + j];
        int c = c0 + tid;
        for (int tok = 0; tok < 16; tok++) {
            float ca = 0.f;
            #pragma unroll
            for (int j = 0; j < 32; j++) ca = fmaf(wv[j], h[tok * 32 + j], ca);
            size_t idx = ((size_t)tg * 16 + tok) * C + c;
            float gate = HG[((size_t)tg * 16 + tok) * FW + 4096 + c];
            float m = mlp[idx] * gate * (1.f + 0.1f * tanhf(ca)) * sv[tok];
            out[idx] = x1[idx] + m;
        }
    }
}

// ---------------- host ----------------
extern "C" void kernel_launch(void* const* d_in, const int* in_sizes, int n_in,
                              void* d_out, int out_size) {
    const float* x        = (const float*)d_in[0];
    const float* ve       = (const float*)d_in[1];
    const float* cosb     = (const float*)d_in[2];
    const float* sinb     = (const float*)d_in[3];
    const float* prev     = (const float*)d_in[4];
    const float* w_q      = (const float*)d_in[5];
    const float* w_k      = (const float*)d_in[6];
    const float* w_v      = (const float*)d_in[7];
    const float* w_o      = (const float*)d_in[8];
    const float* w_veg    = (const float*)d_in[9];
    const float* refine_w = (const float*)d_in[10];
    const float* alpha    = (const float*)d_in[11];
    const float* ca_pi    = (const float*)d_in[12];
    const float* ca_cw    = (const float*)d_in[13];
    const float* ca_po    = (const float*)d_in[14];
    const float* ffn_in   = (const float*)d_in[15];
    const float* ffn_cw   = (const float*)d_in[16];
    const float* ffn_out  = (const float*)d_in[17];
    const float* ffn_gate = (const float*)d_in[18];
    const float* vit_w1   = (const float*)d_in[19];
    const float* vit_w2   = (const float*)d_in[20];
    float* out = (float*)d_out;

    float *XN, *QKV, *WQKV, *Yp, *ATT, *X1, *XM, *WF, *HG, *H2, *MLP, *CR, *CA1, *CA2, *VR, *VIT, *VITF;
    cudaGetSymbolAddress((void**)&XN, g_XN);
    cudaGetSymbolAddress((void**)&QKV, g_QKV);
    cudaGetSymbolAddress((void**)&WQKV, g_WQKV);
    cudaGetSymbolAddress((void**)&Yp, g_Y);
    cudaGetSymbolAddress((void**)&ATT, g_ATT);
    cudaGetSymbolAddress((void**)&X1, g_X1);
    cudaGetSymbolAddress((void**)&XM, g_XM);
    cudaGetSymbolAddress((void**)&WF, g_WF);
    cudaGetSymbolAddress((void**)&HG, g_HG);
    cudaGetSymbolAddress((void**)&H2, g_H2);
    cudaGetSymbolAddress((void**)&MLP, g_MLP);
    cudaGetSymbolAddress((void**)&CR, g_CR);
    cudaGetSymbolAddress((void**)&CA1, g_CA1);
    cudaGetSymbolAddress((void**)&CA2, g_CA2);
    cudaGetSymbolAddress((void**)&VR, g_VR);
    cudaGetSymbolAddress((void**)&VIT, g_VIT);
    cudaGetSymbolAddress((void**)&VITF, g_VITF);

    cudaMemcpyAsync(WQKV,                  w_q, (size_t)1024 * C * 4, cudaMemcpyDeviceToDevice);
    cudaMemcpyAsync(WQKV + 1024 * C,       w_k, (size_t)256 * C * 4, cudaMemcpyDeviceToDevice);
    cudaMemcpyAsync(WQKV + 1280 * C,       w_v, (size_t)256 * C * 4, cudaMemcpyDeviceToDevice);
    cudaMemcpyAsync(WF,                    ffn_in,   (size_t)4096 * C * 4, cudaMemcpyDeviceToDevice);
    cudaMemcpyAsync(WF + (size_t)4096 * C, ffn_gate, (size_t)1024 * C * 4, cudaMemcpyDeviceToDevice);

    k_rmsnorm<<<BT, 256>>>(x, XN);
    k_mgemm<0><<<dim3(QKVW / 128, BT / 128), 256>>>(XN, WQKV, QKV, BT, QKVW, C);
    k_ropegate<<<BT, 256>>>(QKV, XN, ve, cosb, sinb, w_veg);

    int smemf = (3 * 64 * 68 + 66 * 66 + 3 * 64) * (int)sizeof(float);
    cudaFuncSetAttribute(k_flash, cudaFuncAttributeMaxDynamicSharedMemorySize, smemf);
    k_flash<<<dim3(T / 64, NH, BB), 256, smemf>>>(QKV, prev, refine_w, alpha, Yp);

    k_mgemm<0><<<dim3(C / 128, BT / 128), 256>>>(Yp, w_o, ATT, BT, C, C);

    k_dot32<<<BT / 8, 256>>>(x, ca_pi, CR);
    k_caconv<<<dim3(T / 128, BB), 256>>>(CR, ca_cw, CA1);
    k_x1<<<BT / 16, 256>>>(x, ATT, CA1, ca_po, X1);

    k_rmsnorm<<<BT, 256>>>(X1, XM);
    k_mgemm<3><<<dim3(FW / 128, BT / 128), 256>>>(XM, WF, HG, BT, FW, C);
    k_ffnconv<<<dim3(FFNH / 32, T / 64, BB), 256>>>(HG, ffn_cw, H2);
    k_mgemm<0><<<dim3(C / 128, BT / 128), 256>>>(H2, ffn_out, MLP, BT, C, FFNH);

    k_dot32<<<BT / 8, 256>>>(X1, ca_pi, CR);
    k_caconv<<<dim3(T / 128, BB), 256>>>(CR, ca_cw, CA2);
    k_dot32<<<BT / 8, 256>>>(X1, vit_w1, VR);
    k_vitpost<<<BT / 256, 256>>>(VR, vit_w2, VIT);
    k_vsmooth<<<BB, 256>>>(VIT, VITF);

    k_final<<<BT / 16, 256>>>(X1, MLP, HG, CA2, ca_po, VITF, out);
}